// round 12
// baseline (speedup 1.0000x reference)
#include <cuda_runtime.h>
#include <cuda_fp16.h>
#include <math.h>
#include <stdint.h>

#define T_TOK   2048
#define DM      512
#define E_EXP   64
#define TOPK    8
#define H_GATE  1024
#define H_EXP   2048
#define NPAIR   (T_TOK*TOPK)
#define UPART   32
#define KGATE   1536      // concatenated gate K: [x_hi | x_hi | x_lo]

// ---------------- scratch (device globals) ----------------------------------
static __device__ float  g_h[(size_t)T_TOK * H_GATE];
static __device__ float  g_probs[T_TOK * E_EXP];
static __device__ float  g_topkw[T_TOK * TOPK];
static __device__ float  g_part[UPART][E_EXP];
static __device__ int    g_count[E_EXP];
static __device__ int    g_list_t[E_EXP * T_TOK];
static __device__ int    g_list_p[E_EXP * T_TOK];
static __device__ __half g_x16[(size_t)T_TOK * DM];          // x_hi (2 MiB)
static __device__ __half g_gx[(size_t)T_TOK * KGATE];        // [x_hi|x_hi|x_lo] (6 MiB)
static __device__ __half g_gw[(size_t)KGATE * H_GATE];       // [w_hi;w_lo;w_hi] (3 MiB)
static __device__ __half g_hidden16[(size_t)NPAIR * H_EXP];  // 64 MiB
static __device__ float  g_ybuf[(size_t)NPAIR * DM];         // 32 MiB

// ---------------- helpers ----------------------------------------------------
__device__ __forceinline__ uint32_t smem_u32(const void* p) {
    uint32_t a;
    asm("{ .reg .u64 t; cvta.to.shared.u64 t, %1; cvt.u32.u64 %0, t; }" : "=r"(a) : "l"(p));
    return a;
}
__device__ __forceinline__ uint32_t packh(float lo, float hi) {
    uint32_t r;
    asm("cvt.rn.f16x2.f32 %0, %1, %2;" : "=r"(r) : "f"(hi), "f"(lo));
    return r;
}
__device__ __forceinline__ void cp16(uint32_t dst, const void* src, int srcsize) {
    asm volatile("cp.async.cg.shared.global [%0], [%1], 16, %2;"
                 :: "r"(dst), "l"(src), "r"(srcsize) : "memory");
}
__device__ __forceinline__ void cp_commit() {
    asm volatile("cp.async.commit_group;" ::: "memory");
}
__device__ __forceinline__ void ldsm4(uint32_t* r, uint32_t addr) {
    asm volatile("ldmatrix.sync.aligned.m8n8.x4.shared.b16 {%0,%1,%2,%3}, [%4];"
                 : "=r"(r[0]), "=r"(r[1]), "=r"(r[2]), "=r"(r[3]) : "r"(addr));
}
__device__ __forceinline__ void ldsm4t(uint32_t* r, uint32_t addr) {
    asm volatile("ldmatrix.sync.aligned.m8n8.x4.trans.shared.b16 {%0,%1,%2,%3}, [%4];"
                 : "=r"(r[0]), "=r"(r[1]), "=r"(r[2]), "=r"(r[3]) : "r"(addr));
}
__device__ __forceinline__ void mma_f16(float* c, const uint32_t* a, uint32_t b0, uint32_t b1) {
    asm volatile(
        "mma.sync.aligned.m16n8k16.row.col.f32.f16.f16.f32 "
        "{%0,%1,%2,%3}, {%4,%5,%6,%7}, {%8,%9}, {%0,%1,%2,%3};"
        : "+f"(c[0]), "+f"(c[1]), "+f"(c[2]), "+f"(c[3])
        : "r"(a[0]), "r"(a[1]), "r"(a[2]), "r"(a[3]), "r"(b0), "r"(b1));
}

// ---------------- x split: x16 (experts) + concatenated gate A ---------------
__global__ void split_x(const float4* __restrict__ x, uint2* __restrict__ x16,
                        uint2* __restrict__ gx)
{
    const int n4 = T_TOK * DM / 4;
    int stride = gridDim.x * blockDim.x;
    for (int i = blockIdx.x * blockDim.x + threadIdx.x; i < n4; i += stride) {
        float4 v = __ldg(&x[i]);
        __half hx = __float2half_rn(v.x), hy = __float2half_rn(v.y);
        __half hz = __float2half_rn(v.z), hw = __float2half_rn(v.w);
        uint2 h, l;
        h.x = packh(__half2float(hx), __half2float(hy));
        h.y = packh(__half2float(hz), __half2float(hw));
        l.x = packh(v.x - __half2float(hx), v.y - __half2float(hy));
        l.y = packh(v.z - __half2float(hz), v.w - __half2float(hw));
        x16[i] = h;
        int t  = i >> 7;
        int c4 = i & 127;
        uint2* row = gx + (size_t)t * 384;
        row[c4]       = h;
        row[c4 + 128] = h;
        row[c4 + 256] = l;
    }
}

// ---------------- gw1 split: concatenated gate B [w_hi; w_lo; w_hi] ----------
__global__ void split_gw(const float4* __restrict__ w, uint2* __restrict__ gw)
{
    const int n4 = DM * H_GATE / 4;
    int stride = gridDim.x * blockDim.x;
    for (int i = blockIdx.x * blockDim.x + threadIdx.x; i < n4; i += stride) {
        float4 v = __ldg(&w[i]);
        __half hx = __float2half_rn(v.x), hy = __float2half_rn(v.y);
        __half hz = __float2half_rn(v.z), hw = __float2half_rn(v.w);
        uint2 h, l;
        h.x = packh(__half2float(hx), __half2float(hy));
        h.y = packh(__half2float(hz), __half2float(hw));
        l.x = packh(v.x - __half2float(hx), v.y - __half2float(hy));
        l.y = packh(v.z - __half2float(hz), v.w - __half2float(hw));
        int row = i >> 8;
        int c4  = i & 255;
        gw[(size_t)row * 256 + c4]          = h;
        gw[(size_t)(row + 512) * 256 + c4]  = l;
        gw[(size_t)(row + 1024) * 256 + c4] = h;
    }
}

// ---------------- grouped GEMM: cp.async + (opt. fused fp32->fp16) + HMMA ----
// C[out(r), n] = act( sum_k A[in(r), k] * B[e][k, n] + bias[e][n] )
// A fp16. B: fp16 (BF32=0) or fp32 converted in-kernel (BF32=1).
// Tile 128x128, BK=64, 8 warps (32x64). ACT: 0 none, 1 relu, 2 gelu.
// Stage layout: [A16 16KB][B16 16KB][B32 32KB if BF32] ; 3 stages.
template<typename OT, int ACT, int BF32>
__global__ __launch_bounds__(256)
void mma_gemm16(const __half* __restrict__ A, int lda, int K,
                const void* __restrict__ Bbase, size_t strideB, int N,
                const float* __restrict__ biasBase, int strideBias,
                OT* __restrict__ C, int ldc,
                const int* __restrict__ rowlist, const int* __restrict__ outlist,
                const int* __restrict__ cnts, int Mfixed)
{
    constexpr uint32_t STAGE = BF32 ? 65536u : 32768u;

    const int e  = blockIdx.z;
    const int M  = cnts ? cnts[e] : Mfixed;
    const int m0 = blockIdx.x * 128;
    if (m0 >= M) return;
    const int n0 = blockIdx.y * 128;

    extern __shared__ char sm[];
    const uint32_t smBytes = smem_u32(sm);

    const int tid  = threadIdx.x;
    const int wid  = tid >> 5;
    const int lane = tid & 31;
    const int wy   = wid & 3;
    const int wx   = wid >> 2;
    const int g    = lane >> 2;
    const int tig  = lane & 3;

    const int* rl = rowlist ? rowlist + e * T_TOK : nullptr;
    const int* ol = outlist ? outlist + e * T_TOK : nullptr;

    // ---- A staging (gathered fp16 rows) --------------------------------------
    const __half* aSrc[4]; int aSz[4];
    uint32_t aOff0;
    {
        int ar = tid >> 3, s = tid & 7;
        aOff0 = (uint32_t)(ar * 128 + 16 * (s ^ (ar & 7)));
        #pragma unroll
        for (int j = 0; j < 4; j++) {
            int gm = m0 + ar + j * 32;
            if (gm < M) { aSrc[j] = A + (size_t)(rl ? rl[gm] : gm) * lda + s * 8; aSz[j] = 16; }
            else        { aSrc[j] = A;                                            aSz[j] = 0;  }
        }
    }

    // ---- B staging pointers ---------------------------------------------------
    const __half* bSrc16 = nullptr; uint32_t bOff16 = 0;
    const float*  bSrc32 = nullptr; uint32_t bOff32 = 0;
    if (BF32) {
        // fp32 B: row = k, 512B/row, plain seg layout in B32 region
        bSrc32 = (const float*)Bbase + (size_t)e * strideB
               + (size_t)(tid >> 5) * N + n0 + (tid & 31) * 4;
        bOff32 = 32768u + (uint32_t)((tid >> 5) * 512 + (tid & 31) * 16);
    } else {
        bSrc16 = (const __half*)Bbase + (size_t)e * strideB
               + (size_t)(tid >> 4) * N + n0 + (tid & 15) * 8;
        bOff16 = 16384u + (uint32_t)((tid >> 4) * 256 + 16 * ((tid & 15) ^ ((tid >> 4) & 7)));
    }

    const int NC = K / 64;
    const size_t bStep16 = (size_t)64 * N;   // halves per chunk (fp16 path)
    const size_t bStep32 = (size_t)64 * N;   // floats per chunk (fp32 path)

    #define ISSUE(cc) do { \
        uint32_t st = smBytes + (uint32_t)((cc) % 3) * STAGE; \
        _Pragma("unroll") \
        for (int j = 0; j < 4; j++) \
            cp16(st + aOff0 + (uint32_t)j * 4096u, aSrc[j] + (size_t)(cc) * 64, aSz[j]); \
        if (BF32) { \
            _Pragma("unroll") \
            for (int j = 0; j < 8; j++) \
                cp16(st + bOff32 + (uint32_t)j * 4096u, \
                     bSrc32 + (size_t)j * 8 * N + (size_t)(cc) * bStep32, 16); \
        } else { \
            _Pragma("unroll") \
            for (int j = 0; j < 4; j++) \
                cp16(st + bOff16 + (uint32_t)j * 4096u, \
                     bSrc16 + (size_t)j * 16 * N + (size_t)(cc) * bStep16, 16); \
        } \
        cp_commit(); \
    } while (0)

    ISSUE(0);
    if (NC > 1) ISSUE(1);

    float acc[2][8][4];
    #pragma unroll
    for (int fm = 0; fm < 2; fm++)
        #pragma unroll
        for (int fn = 0; fn < 8; fn++)
            #pragma unroll
            for (int q = 0; q < 4; q++) acc[fm][fn][q] = 0.f;

    const int mlane = wy * 32 + (lane & 15);
    const int aksel = (lane >> 4) & 1;
    const int bklan = lane & 15;
    const int bnsel = ((lane >> 4) & 1) * 8;

    for (int c = 0; c < NC; c++) {
        if (c + 1 < NC) asm volatile("cp.async.wait_group 1;" ::: "memory");
        else            asm volatile("cp.async.wait_group 0;" ::: "memory");
        __syncthreads();

        if (c + 2 < NC) ISSUE(c + 2);

        const uint32_t stA = smBytes + (uint32_t)(c % 3) * STAGE;
        const uint32_t stB = stA + 16384u;

        if (BF32) {
            // vectorized fp32 -> fp16 conversion into swizzled B16 layout
            char* base = sm + (size_t)(c % 3) * STAGE;
            const char* s32 = base + 32768;
            char* s16 = base + 16384;
            #pragma unroll
            for (int j = 0; j < 4; j++) {
                int p = tid + j * 256;
                int row = p >> 4, sp = p & 15;
                float4 fa = *(const float4*)(s32 + row * 512 + sp * 32);
                float4 fb = *(const float4*)(s32 + row * 512 + sp * 32 + 16);
                uint4 u;
                u.x = packh(fa.x, fa.y); u.y = packh(fa.z, fa.w);
                u.z = packh(fb.x, fb.y); u.w = packh(fb.z, fb.w);
                *(uint4*)(s16 + row * 256 + 16 * (sp ^ (row & 7))) = u;
            }
            __syncthreads();
        }

        #pragma unroll
        for (int ks = 0; ks < 4; ks++) {
            const int aseg = ks * 2 + aksel;
            uint32_t a0[4], a1[4];
            {
                int m = mlane;
                ldsm4(a0, stA + m * 128 + 16 * (aseg ^ (m & 7)));
                m = mlane + 16;
                ldsm4(a1, stA + m * 128 + 16 * (aseg ^ (m & 7)));
            }
            const int kk = ks * 16 + bklan;
            const uint32_t brow = stB + kk * 256;
            const int ksw = kk & 7;
            #pragma unroll
            for (int nb = 0; nb < 4; nb++) {
                int nseg = (wx * 64 + nb * 16 + bnsel) >> 3;
                uint32_t bb[4];
                ldsm4t(bb, brow + 16 * (nseg ^ ksw));
                mma_f16(acc[0][2 * nb],     a0, bb[0], bb[1]);
                mma_f16(acc[1][2 * nb],     a1, bb[0], bb[1]);
                mma_f16(acc[0][2 * nb + 1], a0, bb[2], bb[3]);
                mma_f16(acc[1][2 * nb + 1], a1, bb[2], bb[3]);
            }
        }
    }
    #undef ISSUE

    // ---- epilogue -----------------------------------------------------------
    const float* bias = biasBase ? biasBase + (size_t)e * strideBias + n0 : nullptr;
    #pragma unroll
    for (int fm = 0; fm < 2; fm++) {
        int r0 = m0 + wy * 32 + fm * 16 + g;
        #pragma unroll
        for (int half = 0; half < 2; half++) {
            int row = r0 + half * 8;
            if (row >= M) continue;
            int orow = ol ? ol[row] : row;
            OT* cp = C + (size_t)orow * ldc + n0;
            #pragma unroll
            for (int fn = 0; fn < 8; fn++) {
                int col = wx * 64 + fn * 8 + 2 * tig;
                float v0 = acc[fm][fn][half * 2 + 0] + (bias ? bias[col]     : 0.f);
                float v1 = acc[fm][fn][half * 2 + 1] + (bias ? bias[col + 1] : 0.f);
                if (ACT == 1) { v0 = fmaxf(v0, 0.f); v1 = fmaxf(v1, 0.f); }
                if (ACT == 2) {
                    v0 = 0.5f * v0 * (1.f + erff(v0 * 0.70710678118654752f));
                    v1 = 0.5f * v1 * (1.f + erff(v1 * 0.70710678118654752f));
                }
                if (sizeof(OT) == 4) {
                    *(float2*)((float*)cp + col) = make_float2(v0, v1);
                } else {
                    *(uint32_t*)((__half*)cp + col) = packh(v0, v1);
                }
            }
        }
    }
}

// ---------------- gating: warp-per-token logits + softmax + top-8 ------------
__global__ __launch_bounds__(256)
void gate_route_kernel(const float* __restrict__ h,
                       const float* __restrict__ w2,
                       const float* __restrict__ b2)
{
    __shared__ float hs[8][H_GATE];
    const int warp = threadIdx.x >> 5;
    const int lane = threadIdx.x & 31;
    const int t0 = blockIdx.x * 8;

    for (int i = threadIdx.x; i < 8 * H_GATE; i += 256)
        hs[i >> 10][i & (H_GATE - 1)] = h[(size_t)(t0 + (i >> 10)) * H_GATE + (i & (H_GATE - 1))];
    __syncthreads();

    const int t = t0 + warp;
    float a0 = b2[lane], a1 = b2[lane + 32];
    const float* hrow = hs[warp];
    #pragma unroll 4
    for (int kk = 0; kk < H_GATE; kk++) {
        float hv = hrow[kk];
        a0 = fmaf(hv, __ldg(&w2[kk * E_EXP + lane]),      a0);
        a1 = fmaf(hv, __ldg(&w2[kk * E_EXP + lane + 32]), a1);
    }

    float mx = fmaxf(a0, a1);
    #pragma unroll
    for (int s = 16; s; s >>= 1) mx = fmaxf(mx, __shfl_xor_sync(~0u, mx, s));
    float p0 = expf(a0 - mx), p1 = expf(a1 - mx);
    float sum = p0 + p1;
    #pragma unroll
    for (int s = 16; s; s >>= 1) sum += __shfl_xor_sync(~0u, sum, s);
    p0 /= sum; p1 /= sum;
    g_probs[t * E_EXP + lane]      = p0;
    g_probs[t * E_EXP + lane + 32] = p1;

    float v0 = p0, v1 = p1;
    float selw[TOPK]; int seli[TOPK];
    #pragma unroll
    for (int k = 0; k < TOPK; k++) {
        float v; int idx;
        if (v0 >= v1) { v = v0; idx = lane; } else { v = v1; idx = lane + 32; }
        #pragma unroll
        for (int s = 16; s; s >>= 1) {
            float ov = __shfl_xor_sync(~0u, v, s);
            int   oi = __shfl_xor_sync(~0u, idx, s);
            if (ov > v || (ov == v && oi < idx)) { v = ov; idx = oi; }
        }
        selw[k] = v; seli[k] = idx;
        if (idx == lane) v0 = -1.f;
        else if (idx == lane + 32) v1 = -1.f;
    }

    if (lane == 0) {
        float s8 = 0.f;
        #pragma unroll
        for (int k = 0; k < TOPK; k++) s8 += selw[k];
        float inv = 1.f / s8;
        #pragma unroll
        for (int k = 0; k < TOPK; k++) {
            int ee = seli[k];
            g_topkw[t * TOPK + k] = selw[k] * inv;
            int pos = atomicAdd(&g_count[ee], 1);
            g_list_t[ee * T_TOK + pos] = t;
            g_list_p[ee * T_TOK + pos] = t * TOPK + k;
        }
    }
}

// ---------------- load-balance loss (coalesced two-phase) --------------------
__global__ void usage_part()
{
    __shared__ float red[4][E_EXP];
    const int b   = blockIdx.x;
    const int e   = threadIdx.x & 63;
    const int sub = threadIdx.x >> 6;
    float s = 0.f;
    #pragma unroll
    for (int i = 0; i < 16; i++) {
        int t = b * 64 + i * 4 + sub;
        s += g_probs[t * E_EXP + e];
    }
    red[sub][e] = s; __syncthreads();
    if (sub == 0)
        g_part[b][e] = red[0][e] + red[1][e] + red[2][e] + red[3][e];
}
__global__ void lb_final(float* __restrict__ out, int out_size)
{
    __shared__ float red[E_EXP];
    const int e = threadIdx.x;
    float s = 0.f;
    #pragma unroll
    for (int b = 0; b < UPART; b++) s += g_part[b][e];
    float u = s / (float)T_TOK - 1.f / (float)E_EXP;
    red[e] = u * u; __syncthreads();
    for (int st = 32; st > 0; st >>= 1) { if (e < st) red[e] += red[e + st]; __syncthreads(); }
    if (e == 0 && out_size > T_TOK * DM)
        out[T_TOK * DM] = 0.01f * red[0] / (float)E_EXP;
}

// ---------------- weighted combine (float4, one token per block) -------------
__global__ __launch_bounds__(128)
void combine_kernel(float* __restrict__ out)
{
    const int t = blockIdx.x;
    const int d4 = threadIdx.x;
    const float4* yb = (const float4*)g_ybuf;
    float4 a = make_float4(0.f, 0.f, 0.f, 0.f);
    #pragma unroll
    for (int k = 0; k < TOPK; k++) {
        float w = g_topkw[t * TOPK + k];
        float4 y = yb[(size_t)(t * TOPK + k) * (DM / 4) + d4];
        a.x = fmaf(w, y.x, a.x); a.y = fmaf(w, y.y, a.y);
        a.z = fmaf(w, y.z, a.z); a.w = fmaf(w, y.w, a.w);
    }
    ((float4*)out)[(size_t)t * (DM / 4) + d4] = a;
}

__global__ void zero_counts() { g_count[threadIdx.x] = 0; }

// ---------------- launch ------------------------------------------------------
extern "C" void kernel_launch(void* const* d_in, const int* in_sizes, int n_in,
                              void* d_out, int out_size)
{
    const float* x   = (const float*)d_in[0];
    const float* gw1 = (const float*)d_in[1];
    const float* gb1 = (const float*)d_in[2];
    const float* gw2 = (const float*)d_in[3];
    const float* gb2 = (const float*)d_in[4];
    const float* ew1 = (const float*)d_in[5];
    const float* eb1 = (const float*)d_in[6];
    const float* ew2 = (const float*)d_in[7];
    const float* eb2 = (const float*)d_in[8];
    float* out = (float*)d_out;

    float *ph, *pybuf;
    __half *phid, *px16, *pgx, *pgw;
    int *pcnt, *plt, *plp;
    cudaGetSymbolAddress((void**)&ph,    g_h);
    cudaGetSymbolAddress((void**)&phid,  g_hidden16);
    cudaGetSymbolAddress((void**)&px16,  g_x16);
    cudaGetSymbolAddress((void**)&pgx,   g_gx);
    cudaGetSymbolAddress((void**)&pgw,   g_gw);
    cudaGetSymbolAddress((void**)&pybuf, g_ybuf);
    cudaGetSymbolAddress((void**)&pcnt,  g_count);
    cudaGetSymbolAddress((void**)&plt,   g_list_t);
    cudaGetSymbolAddress((void**)&plp,   g_list_p);

    const int SMEM_16 = 3 * 32768;    // 96 KB  (fp16-B path: gate GEMM)
    const int SMEM_32 = 3 * 65536;    // 192 KB (fused fp32-B path: expert GEMMs)
    cudaFuncSetAttribute((const void*)mma_gemm16<float, 1, 0>,
                         cudaFuncAttributeMaxDynamicSharedMemorySize, SMEM_16);
    cudaFuncSetAttribute((const void*)mma_gemm16<__half, 2, 1>,
                         cudaFuncAttributeMaxDynamicSharedMemorySize, SMEM_32);
    cudaFuncSetAttribute((const void*)mma_gemm16<float, 0, 1>,
                         cudaFuncAttributeMaxDynamicSharedMemorySize, SMEM_32);

    zero_counts<<<1, E_EXP>>>();
    split_x<<<512, 256>>>((const float4*)x, (uint2*)px16, (uint2*)pgx);
    split_gw<<<512, 256>>>((const float4*)gw1, (uint2*)pgw);

    // gate layer 1, single error-compensated GEMM (K=1536, fp16 B)
    mma_gemm16<float, 1, 0><<<dim3(T_TOK/128, H_GATE/128, 1), 256, SMEM_16>>>(
        pgx, KGATE, KGATE, pgw, 0, H_GATE, gb1, 0,
        ph, H_GATE, nullptr, nullptr, nullptr, T_TOK);

    gate_route_kernel<<<T_TOK / 8, 256>>>(ph, gw2, gb2);

    usage_part<<<UPART, 256>>>();
    lb_final<<<1, E_EXP>>>(out, out_size);

    // expert GEMM 1: hidden16 = gelu(x16[list] @ ew1[e] + eb1[e]) — fused fp32 B
    mma_gemm16<__half, 2, 1><<<dim3(T_TOK/128, H_EXP/128, E_EXP), 256, SMEM_32>>>(
        px16, DM, DM, ew1, (size_t)DM * H_EXP, H_EXP, eb1, H_EXP,
        phid, H_EXP, plt, plp, pcnt, 0);

    // expert GEMM 2: ybuf = hidden16[list] @ ew2[e] + eb2[e] — fused fp32 B
    mma_gemm16<float, 0, 1><<<dim3(T_TOK/128, DM/128, E_EXP), 256, SMEM_32>>>(
        phid, H_EXP, H_EXP, ew2, (size_t)H_EXP * DM, DM, eb2, DM,
        pybuf, DM, plp, plp, pcnt, 0);

    combine_kernel<<<T_TOK, 128>>>(out);
}

// round 13
// speedup vs baseline: 1.6961x; 1.6961x over previous
#include <cuda_runtime.h>
#include <cuda_fp16.h>
#include <math.h>
#include <stdint.h>

#define T_TOK   2048
#define DM      512
#define E_EXP   64
#define TOPK    8
#define H_GATE  1024
#define H_EXP   2048
#define NPAIR   (T_TOK*TOPK)
#define UPART   32
#define KGATE   1536      // concatenated gate K: [x_hi | x_hi | x_lo]

// ---------------- scratch (device globals) ----------------------------------
static __device__ float  g_h[(size_t)T_TOK * H_GATE];
static __device__ float  g_probs[T_TOK * E_EXP];
static __device__ float  g_topkw[T_TOK * TOPK];
static __device__ float  g_part[UPART][E_EXP];
static __device__ int    g_count[E_EXP];
static __device__ int    g_list_t[E_EXP * T_TOK];
static __device__ int    g_list_p[E_EXP * T_TOK];
static __device__ __half g_x16[(size_t)T_TOK * DM];          // x_hi (2 MiB)
static __device__ __half g_gx[(size_t)T_TOK * KGATE];        // [x_hi|x_hi|x_lo] (6 MiB)
static __device__ __half g_gw[(size_t)KGATE * H_GATE];       // [w_hi;w_lo;w_hi] (3 MiB)
static __device__ __half g_w1h[(size_t)E_EXP * DM * H_EXP];  // 128 MiB
static __device__ __half g_w2h[(size_t)E_EXP * H_EXP * DM];  // 128 MiB
static __device__ __half g_hidden16[(size_t)NPAIR * H_EXP];  // 64 MiB
static __device__ float  g_ybuf[(size_t)NPAIR * DM];         // 32 MiB

// ---------------- helpers ----------------------------------------------------
__device__ __forceinline__ uint32_t smem_u32(const void* p) {
    uint32_t a;
    asm("{ .reg .u64 t; cvta.to.shared.u64 t, %1; cvt.u32.u64 %0, t; }" : "=r"(a) : "l"(p));
    return a;
}
__device__ __forceinline__ uint32_t packh(float lo, float hi) {
    uint32_t r;
    asm("cvt.rn.f16x2.f32 %0, %1, %2;" : "=r"(r) : "f"(hi), "f"(lo));
    return r;
}
__device__ __forceinline__ void cp16(uint32_t dst, const void* src, int srcsize) {
    asm volatile("cp.async.cg.shared.global [%0], [%1], 16, %2;"
                 :: "r"(dst), "l"(src), "r"(srcsize) : "memory");
}
__device__ __forceinline__ void cp_commit() {
    asm volatile("cp.async.commit_group;" ::: "memory");
}
__device__ __forceinline__ void ldsm4(uint32_t* r, uint32_t addr) {
    asm volatile("ldmatrix.sync.aligned.m8n8.x4.shared.b16 {%0,%1,%2,%3}, [%4];"
                 : "=r"(r[0]), "=r"(r[1]), "=r"(r[2]), "=r"(r[3]) : "r"(addr));
}
__device__ __forceinline__ void ldsm4t(uint32_t* r, uint32_t addr) {
    asm volatile("ldmatrix.sync.aligned.m8n8.x4.trans.shared.b16 {%0,%1,%2,%3}, [%4];"
                 : "=r"(r[0]), "=r"(r[1]), "=r"(r[2]), "=r"(r[3]) : "r"(addr));
}
__device__ __forceinline__ void mma_f16(float* c, const uint32_t* a, uint32_t b0, uint32_t b1) {
    asm volatile(
        "mma.sync.aligned.m16n8k16.row.col.f32.f16.f16.f32 "
        "{%0,%1,%2,%3}, {%4,%5,%6,%7}, {%8,%9}, {%0,%1,%2,%3};"
        : "+f"(c[0]), "+f"(c[1]), "+f"(c[2]), "+f"(c[3])
        : "r"(a[0]), "r"(a[1]), "r"(a[2]), "r"(a[3]), "r"(b0), "r"(b1));
}

// ---------------- fp32 -> fp16 bulk convert (grid-stride, saturating) --------
__global__ void cvt16(const float4* __restrict__ in, uint4* __restrict__ out, int n8)
{
    int stride = gridDim.x * blockDim.x;
    for (int i = blockIdx.x * blockDim.x + threadIdx.x; i < n8; i += stride) {
        float4 v0 = __ldg(&in[2 * i]);
        float4 v1 = __ldg(&in[2 * i + 1]);
        uint4 o;
        o.x = packh(v0.x, v0.y); o.y = packh(v0.z, v0.w);
        o.z = packh(v1.x, v1.y); o.w = packh(v1.z, v1.w);
        out[i] = o;
    }
}

// ---------------- x split: x16 + concatenated gate A (+count zeroing) --------
__global__ void split_x(const float4* __restrict__ x, uint2* __restrict__ x16,
                        uint2* __restrict__ gx)
{
    if (blockIdx.x == 0 && threadIdx.x < E_EXP) g_count[threadIdx.x] = 0;
    const int n4 = T_TOK * DM / 4;
    int stride = gridDim.x * blockDim.x;
    for (int i = blockIdx.x * blockDim.x + threadIdx.x; i < n4; i += stride) {
        float4 v = __ldg(&x[i]);
        __half hx = __float2half_rn(v.x), hy = __float2half_rn(v.y);
        __half hz = __float2half_rn(v.z), hw = __float2half_rn(v.w);
        uint2 h, l;
        h.x = packh(__half2float(hx), __half2float(hy));
        h.y = packh(__half2float(hz), __half2float(hw));
        l.x = packh(v.x - __half2float(hx), v.y - __half2float(hy));
        l.y = packh(v.z - __half2float(hz), v.w - __half2float(hw));
        x16[i] = h;
        int t  = i >> 7;
        int c4 = i & 127;
        uint2* row = gx + (size_t)t * 384;
        row[c4]       = h;
        row[c4 + 128] = h;
        row[c4 + 256] = l;
    }
}

// ---------------- gw1 split: concatenated gate B [w_hi; w_lo; w_hi] ----------
__global__ void split_gw(const float4* __restrict__ w, uint2* __restrict__ gw)
{
    const int n4 = DM * H_GATE / 4;
    int stride = gridDim.x * blockDim.x;
    for (int i = blockIdx.x * blockDim.x + threadIdx.x; i < n4; i += stride) {
        float4 v = __ldg(&w[i]);
        __half hx = __float2half_rn(v.x), hy = __float2half_rn(v.y);
        __half hz = __float2half_rn(v.z), hw = __float2half_rn(v.w);
        uint2 h, l;
        h.x = packh(__half2float(hx), __half2float(hy));
        h.y = packh(__half2float(hz), __half2float(hw));
        l.x = packh(v.x - __half2float(hx), v.y - __half2float(hy));
        l.y = packh(v.z - __half2float(hz), v.w - __half2float(hw));
        int row = i >> 8;
        int c4  = i & 255;
        gw[(size_t)row * 256 + c4]          = h;
        gw[(size_t)(row + 512) * 256 + c4]  = l;
        gw[(size_t)(row + 1024) * 256 + c4] = h;
    }
}

// ---------------- all-fp16 grouped GEMM: cp.async + ldmatrix + HMMA ----------
// C[out(r), n] = act( sum_k A[in(r), k] * B[e][k, n] + bias[e][n] )
// Tile 128x128, BK=64, 8 warps (32x64). ACT: 0 none, 1 relu, 2 gelu.
template<typename OT, int ACT>
__global__ __launch_bounds__(256, 2)
void mma_gemm16(const __half* __restrict__ A, int lda, int K,
                const __half* __restrict__ Bbase, size_t strideB, int N,
                const float* __restrict__ biasBase, int strideBias,
                OT* __restrict__ C, int ldc,
                const int* __restrict__ rowlist, const int* __restrict__ outlist,
                const int* __restrict__ cnts, int Mfixed)
{
    const int e  = blockIdx.z;
    const int M  = cnts ? cnts[e] : Mfixed;
    const int m0 = blockIdx.x * 128;
    if (m0 >= M) return;
    const int n0 = blockIdx.y * 128;

    extern __shared__ char sm[];
    const uint32_t smBytes = smem_u32(sm);

    const int tid  = threadIdx.x;
    const int wid  = tid >> 5;
    const int lane = tid & 31;
    const int wy   = wid & 3;
    const int wx   = wid >> 2;
    const int g    = lane >> 2;
    const int tig  = lane & 3;

    const int* rl = rowlist ? rowlist + e * T_TOK : nullptr;
    const int* ol = outlist ? outlist + e * T_TOK : nullptr;

    const __half* aSrc[4]; int aSz[4];
    uint32_t aOff0, bOff0;
    const __half* bSrc0;
    {
        int ar = tid >> 3, s = tid & 7;
        aOff0 = (uint32_t)(ar * 128 + 16 * (s ^ (ar & 7)));
        #pragma unroll
        for (int j = 0; j < 4; j++) {
            int gm = m0 + ar + j * 32;
            if (gm < M) { aSrc[j] = A + (size_t)(rl ? rl[gm] : gm) * lda + s * 8; aSz[j] = 16; }
            else        { aSrc[j] = A;                                            aSz[j] = 0;  }
        }
        int bk = tid >> 4, s2 = tid & 15;
        bOff0 = 16384u + (uint32_t)(bk * 256 + 16 * (s2 ^ (bk & 7)));
        bSrc0 = Bbase + (size_t)e * strideB + (size_t)bk * N + n0 + s2 * 8;
    }

    const int NC = K / 64;
    const size_t bStep = (size_t)64 * N;

    #define ISSUE(cc) do { \
        uint32_t st = smBytes + (uint32_t)((cc) % 3) * 32768u; \
        _Pragma("unroll") \
        for (int j = 0; j < 4; j++) \
            cp16(st + aOff0 + (uint32_t)j * 4096u, aSrc[j] + (size_t)(cc) * 64, aSz[j]); \
        _Pragma("unroll") \
        for (int j = 0; j < 4; j++) \
            cp16(st + bOff0 + (uint32_t)j * 4096u, bSrc0 + (size_t)j * 16 * N + (size_t)(cc) * bStep, 16); \
        cp_commit(); \
    } while (0)

    ISSUE(0);
    if (NC > 1) ISSUE(1);

    float acc[2][8][4];
    #pragma unroll
    for (int fm = 0; fm < 2; fm++)
        #pragma unroll
        for (int fn = 0; fn < 8; fn++)
            #pragma unroll
            for (int q = 0; q < 4; q++) acc[fm][fn][q] = 0.f;

    const int mlane = wy * 32 + (lane & 15);
    const int aksel = (lane >> 4) & 1;
    const int bklan = lane & 15;
    const int bnsel = ((lane >> 4) & 1) * 8;

    for (int c = 0; c < NC; c++) {
        if (c + 1 < NC) asm volatile("cp.async.wait_group 1;" ::: "memory");
        else            asm volatile("cp.async.wait_group 0;" ::: "memory");
        __syncthreads();

        if (c + 2 < NC) ISSUE(c + 2);

        const uint32_t stA = smBytes + (uint32_t)(c % 3) * 32768u;
        const uint32_t stB = stA + 16384u;

        #pragma unroll
        for (int ks = 0; ks < 4; ks++) {
            const int aseg = ks * 2 + aksel;
            uint32_t a0[4], a1[4];
            {
                int m = mlane;
                ldsm4(a0, stA + m * 128 + 16 * (aseg ^ (m & 7)));
                m = mlane + 16;
                ldsm4(a1, stA + m * 128 + 16 * (aseg ^ (m & 7)));
            }
            const int kk = ks * 16 + bklan;
            const uint32_t brow = stB + kk * 256;
            const int ksw = kk & 7;
            #pragma unroll
            for (int nb = 0; nb < 4; nb++) {
                int nseg = (wx * 64 + nb * 16 + bnsel) >> 3;
                uint32_t bb[4];
                ldsm4t(bb, brow + 16 * (nseg ^ ksw));
                mma_f16(acc[0][2 * nb],     a0, bb[0], bb[1]);
                mma_f16(acc[1][2 * nb],     a1, bb[0], bb[1]);
                mma_f16(acc[0][2 * nb + 1], a0, bb[2], bb[3]);
                mma_f16(acc[1][2 * nb + 1], a1, bb[2], bb[3]);
            }
        }
    }
    #undef ISSUE

    // ---- epilogue -----------------------------------------------------------
    const float* bias = biasBase ? biasBase + (size_t)e * strideBias + n0 : nullptr;
    #pragma unroll
    for (int fm = 0; fm < 2; fm++) {
        int r0 = m0 + wy * 32 + fm * 16 + g;
        #pragma unroll
        for (int half = 0; half < 2; half++) {
            int row = r0 + half * 8;
            if (row >= M) continue;
            int orow = ol ? ol[row] : row;
            OT* cp = C + (size_t)orow * ldc + n0;
            #pragma unroll
            for (int fn = 0; fn < 8; fn++) {
                int col = wx * 64 + fn * 8 + 2 * tig;
                float v0 = acc[fm][fn][half * 2 + 0] + (bias ? bias[col]     : 0.f);
                float v1 = acc[fm][fn][half * 2 + 1] + (bias ? bias[col + 1] : 0.f);
                if (ACT == 1) { v0 = fmaxf(v0, 0.f); v1 = fmaxf(v1, 0.f); }
                if (ACT == 2) {
                    v0 = 0.5f * v0 * (1.f + erff(v0 * 0.70710678118654752f));
                    v1 = 0.5f * v1 * (1.f + erff(v1 * 0.70710678118654752f));
                }
                if (sizeof(OT) == 4) {
                    *(float2*)((float*)cp + col) = make_float2(v0, v1);
                } else {
                    *(uint32_t*)((__half*)cp + col) = packh(v0, v1);
                }
            }
        }
    }
}

// ---------------- gating: warp-per-token logits + softmax + top-8 ------------
__global__ __launch_bounds__(256)
void gate_route_kernel(const float* __restrict__ h,
                       const float* __restrict__ w2,
                       const float* __restrict__ b2)
{
    __shared__ float hs[8][H_GATE];
    const int warp = threadIdx.x >> 5;
    const int lane = threadIdx.x & 31;
    const int t0 = blockIdx.x * 8;

    for (int i = threadIdx.x; i < 8 * H_GATE; i += 256)
        hs[i >> 10][i & (H_GATE - 1)] = h[(size_t)(t0 + (i >> 10)) * H_GATE + (i & (H_GATE - 1))];
    __syncthreads();

    const int t = t0 + warp;
    float a0 = b2[lane], a1 = b2[lane + 32];
    const float* hrow = hs[warp];
    #pragma unroll 4
    for (int kk = 0; kk < H_GATE; kk++) {
        float hv = hrow[kk];
        a0 = fmaf(hv, __ldg(&w2[kk * E_EXP + lane]),      a0);
        a1 = fmaf(hv, __ldg(&w2[kk * E_EXP + lane + 32]), a1);
    }

    float mx = fmaxf(a0, a1);
    #pragma unroll
    for (int s = 16; s; s >>= 1) mx = fmaxf(mx, __shfl_xor_sync(~0u, mx, s));
    float p0 = expf(a0 - mx), p1 = expf(a1 - mx);
    float sum = p0 + p1;
    #pragma unroll
    for (int s = 16; s; s >>= 1) sum += __shfl_xor_sync(~0u, sum, s);
    p0 /= sum; p1 /= sum;
    g_probs[t * E_EXP + lane]      = p0;
    g_probs[t * E_EXP + lane + 32] = p1;

    float v0 = p0, v1 = p1;
    float selw[TOPK]; int seli[TOPK];
    #pragma unroll
    for (int k = 0; k < TOPK; k++) {
        float v; int idx;
        if (v0 >= v1) { v = v0; idx = lane; } else { v = v1; idx = lane + 32; }
        #pragma unroll
        for (int s = 16; s; s >>= 1) {
            float ov = __shfl_xor_sync(~0u, v, s);
            int   oi = __shfl_xor_sync(~0u, idx, s);
            if (ov > v || (ov == v && oi < idx)) { v = ov; idx = oi; }
        }
        selw[k] = v; seli[k] = idx;
        if (idx == lane) v0 = -1.f;
        else if (idx == lane + 32) v1 = -1.f;
    }

    if (lane == 0) {
        float s8 = 0.f;
        #pragma unroll
        for (int k = 0; k < TOPK; k++) s8 += selw[k];
        float inv = 1.f / s8;
        #pragma unroll
        for (int k = 0; k < TOPK; k++) {
            int ee = seli[k];
            g_topkw[t * TOPK + k] = selw[k] * inv;
            int pos = atomicAdd(&g_count[ee], 1);
            g_list_t[ee * T_TOK + pos] = t;
            g_list_p[ee * T_TOK + pos] = t * TOPK + k;
        }
    }
}

// ---------------- load-balance loss (coalesced two-phase) --------------------
__global__ void usage_part()
{
    __shared__ float red[4][E_EXP];
    const int b   = blockIdx.x;
    const int e   = threadIdx.x & 63;
    const int sub = threadIdx.x >> 6;
    float s = 0.f;
    #pragma unroll
    for (int i = 0; i < 16; i++) {
        int t = b * 64 + i * 4 + sub;
        s += g_probs[t * E_EXP + e];
    }
    red[sub][e] = s; __syncthreads();
    if (sub == 0)
        g_part[b][e] = red[0][e] + red[1][e] + red[2][e] + red[3][e];
}
__global__ void lb_final(float* __restrict__ out, int out_size)
{
    __shared__ float red[E_EXP];
    const int e = threadIdx.x;
    float s = 0.f;
    #pragma unroll
    for (int b = 0; b < UPART; b++) s += g_part[b][e];
    float u = s / (float)T_TOK - 1.f / (float)E_EXP;
    red[e] = u * u; __syncthreads();
    for (int st = 32; st > 0; st >>= 1) { if (e < st) red[e] += red[e + st]; __syncthreads(); }
    if (e == 0 && out_size > T_TOK * DM)
        out[T_TOK * DM] = 0.01f * red[0] / (float)E_EXP;
}

// ---------------- weighted combine (float4, one token per block) -------------
__global__ __launch_bounds__(128)
void combine_kernel(float* __restrict__ out)
{
    const int t = blockIdx.x;
    const int d4 = threadIdx.x;
    const float4* yb = (const float4*)g_ybuf;
    float4 a = make_float4(0.f, 0.f, 0.f, 0.f);
    #pragma unroll
    for (int k = 0; k < TOPK; k++) {
        float w = g_topkw[t * TOPK + k];
        float4 y = yb[(size_t)(t * TOPK + k) * (DM / 4) + d4];
        a.x = fmaf(w, y.x, a.x); a.y = fmaf(w, y.y, a.y);
        a.z = fmaf(w, y.z, a.z); a.w = fmaf(w, y.w, a.w);
    }
    ((float4*)out)[(size_t)t * (DM / 4) + d4] = a;
}

// ---------------- launch ------------------------------------------------------
extern "C" void kernel_launch(void* const* d_in, const int* in_sizes, int n_in,
                              void* d_out, int out_size)
{
    const float* x   = (const float*)d_in[0];
    const float* gw1 = (const float*)d_in[1];
    const float* gb1 = (const float*)d_in[2];
    const float* gw2 = (const float*)d_in[3];
    const float* gb2 = (const float*)d_in[4];
    const float* ew1 = (const float*)d_in[5];
    const float* eb1 = (const float*)d_in[6];
    const float* ew2 = (const float*)d_in[7];
    const float* eb2 = (const float*)d_in[8];
    float* out = (float*)d_out;

    float *ph, *pybuf;
    __half *phid, *px16, *pgx, *pgw, *pw1h, *pw2h;
    int *pcnt, *plt, *plp;
    cudaGetSymbolAddress((void**)&ph,    g_h);
    cudaGetSymbolAddress((void**)&phid,  g_hidden16);
    cudaGetSymbolAddress((void**)&px16,  g_x16);
    cudaGetSymbolAddress((void**)&pgx,   g_gx);
    cudaGetSymbolAddress((void**)&pgw,   g_gw);
    cudaGetSymbolAddress((void**)&pw1h,  g_w1h);
    cudaGetSymbolAddress((void**)&pw2h,  g_w2h);
    cudaGetSymbolAddress((void**)&pybuf, g_ybuf);
    cudaGetSymbolAddress((void**)&pcnt,  g_count);
    cudaGetSymbolAddress((void**)&plt,   g_list_t);
    cudaGetSymbolAddress((void**)&plp,   g_list_p);

    const int SMEM_DYN = 3 * 32768;   // 96 KB
    cudaFuncSetAttribute((const void*)mma_gemm16<float, 1>,
                         cudaFuncAttributeMaxDynamicSharedMemorySize, SMEM_DYN);
    cudaFuncSetAttribute((const void*)mma_gemm16<__half, 2>,
                         cudaFuncAttributeMaxDynamicSharedMemorySize, SMEM_DYN);
    cudaFuncSetAttribute((const void*)mma_gemm16<float, 0>,
                         cudaFuncAttributeMaxDynamicSharedMemorySize, SMEM_DYN);

    // fp16 weight conversions (grid-stride, DRAM-saturating)
    {
        int n8w = (E_EXP * DM * H_EXP) / 8;
        cvt16<<<4096, 256>>>((const float4*)ew1, (uint4*)pw1h, n8w);
        cvt16<<<4096, 256>>>((const float4*)ew2, (uint4*)pw2h, n8w);
    }

    // gate path
    split_x<<<512, 256>>>((const float4*)x, (uint2*)px16, (uint2*)pgx);
    split_gw<<<512, 256>>>((const float4*)gw1, (uint2*)pgw);

    // gate layer 1, single error-compensated GEMM (K=1536, fp32-class precision)
    mma_gemm16<float, 1><<<dim3(T_TOK/128, H_GATE/128, 1), 256, SMEM_DYN>>>(
        pgx, KGATE, KGATE, pgw, 0, H_GATE, gb1, 0,
        ph, H_GATE, nullptr, nullptr, nullptr, T_TOK);

    gate_route_kernel<<<T_TOK / 8, 256>>>(ph, gw2, gb2);

    usage_part<<<UPART, 256>>>();
    lb_final<<<1, E_EXP>>>(out, out_size);

    // expert GEMM 1: hidden16 = gelu(x16[list] @ w1h[e] + eb1[e])
    mma_gemm16<__half, 2><<<dim3(T_TOK/128, H_EXP/128, E_EXP), 256, SMEM_DYN>>>(
        px16, DM, DM, pw1h, (size_t)DM * H_EXP, H_EXP, eb1, H_EXP,
        phid, H_EXP, plt, plp, pcnt, 0);

    // expert GEMM 2: ybuf = hidden16[list] @ w2h[e] + eb2[e]
    mma_gemm16<float, 0><<<dim3(T_TOK/128, DM/128, E_EXP), 256, SMEM_DYN>>>(
        phid, H_EXP, H_EXP, pw2h, (size_t)H_EXP * DM, DM, eb2, DM,
        pybuf, DM, plp, plp, pcnt, 0);

    combine_kernel<<<T_TOK, 128>>>(out);
}

// round 14
// speedup vs baseline: 1.7254x; 1.0172x over previous
#include <cuda_runtime.h>
#include <cuda_fp16.h>
#include <math.h>
#include <stdint.h>

#define T_TOK   2048
#define DM      512
#define E_EXP   64
#define TOPK    8
#define H_GATE  1024
#define H_EXP   2048
#define NPAIR   (T_TOK*TOPK)
#define UPART   32
#define KGATE   1536
#define MAXBLK  192       // sum_e ceil(cnt_e/128) <= 16384/128 + 63 = 191

// ---------------- scratch (device globals) ----------------------------------
static __device__ float  g_h[(size_t)T_TOK * H_GATE];
static __device__ float  g_probs[T_TOK * E_EXP];
static __device__ float  g_topkw[T_TOK * TOPK];
static __device__ float  g_part[UPART][E_EXP];
static __device__ int    g_count[E_EXP];
static __device__ int    g_list_t[E_EXP * T_TOK];
static __device__ int    g_list_p[E_EXP * T_TOK];
static __device__ int2   g_btab[MAXBLK + 1];
static __device__ int    g_nblk;
static __device__ __half g_x16[(size_t)T_TOK * DM];
static __device__ __half g_gx[(size_t)T_TOK * KGATE];
static __device__ __half g_gw[(size_t)KGATE * H_GATE];
static __device__ __half g_w1h[(size_t)E_EXP * DM * H_EXP];
static __device__ __half g_w2h[(size_t)E_EXP * H_EXP * DM];
static __device__ __half g_hidden16[(size_t)NPAIR * H_EXP];
static __device__ float  g_ybuf[(size_t)NPAIR * DM];

// ---------------- helpers ----------------------------------------------------
__device__ __forceinline__ uint32_t smem_u32(const void* p) {
    uint32_t a;
    asm("{ .reg .u64 t; cvta.to.shared.u64 t, %1; cvt.u32.u64 %0, t; }" : "=r"(a) : "l"(p));
    return a;
}
__device__ __forceinline__ uint32_t packh(float lo, float hi) {
    uint32_t r;
    asm("cvt.rn.f16x2.f32 %0, %1, %2;" : "=r"(r) : "f"(hi), "f"(lo));
    return r;
}
__device__ __forceinline__ void cp16(uint32_t dst, const void* src, int srcsize) {
    asm volatile("cp.async.cg.shared.global [%0], [%1], 16, %2;"
                 :: "r"(dst), "l"(src), "r"(srcsize) : "memory");
}
__device__ __forceinline__ void cp_commit() {
    asm volatile("cp.async.commit_group;" ::: "memory");
}
__device__ __forceinline__ void ldsm4(uint32_t* r, uint32_t addr) {
    asm volatile("ldmatrix.sync.aligned.m8n8.x4.shared.b16 {%0,%1,%2,%3}, [%4];"
                 : "=r"(r[0]), "=r"(r[1]), "=r"(r[2]), "=r"(r[3]) : "r"(addr));
}
__device__ __forceinline__ void ldsm4t(uint32_t* r, uint32_t addr) {
    asm volatile("ldmatrix.sync.aligned.m8n8.x4.trans.shared.b16 {%0,%1,%2,%3}, [%4];"
                 : "=r"(r[0]), "=r"(r[1]), "=r"(r[2]), "=r"(r[3]) : "r"(addr));
}
__device__ __forceinline__ void mma_f16(float* c, const uint32_t* a, uint32_t b0, uint32_t b1) {
    asm volatile(
        "mma.sync.aligned.m16n8k16.row.col.f32.f16.f16.f32 "
        "{%0,%1,%2,%3}, {%4,%5,%6,%7}, {%8,%9}, {%0,%1,%2,%3};"
        : "+f"(c[0]), "+f"(c[1]), "+f"(c[2]), "+f"(c[3])
        : "r"(a[0]), "r"(a[1]), "r"(a[2]), "r"(a[3]), "r"(b0), "r"(b1));
}

// ---------------- fused fp32 -> fp16 bulk convert (w1 then w2) ---------------
__global__ void cvt16_w(const float4* __restrict__ w1, uint4* __restrict__ o1,
                        const float4* __restrict__ w2, uint4* __restrict__ o2,
                        int n8each)
{
    int stride = gridDim.x * blockDim.x;
    int total = 2 * n8each;
    for (int i = blockIdx.x * blockDim.x + threadIdx.x; i < total; i += stride) {
        const float4* in; uint4* out; int j;
        if (i < n8each) { in = w1; out = o1; j = i; }
        else            { in = w2; out = o2; j = i - n8each; }
        float4 v0 = __ldg(&in[2 * j]);
        float4 v1 = __ldg(&in[2 * j + 1]);
        uint4 o;
        o.x = packh(v0.x, v0.y); o.y = packh(v0.z, v0.w);
        o.z = packh(v1.x, v1.y); o.w = packh(v1.z, v1.w);
        out[j] = o;
    }
}

// ---------------- fused split: blocks [0,512) x-split, [512,1024) gw-split ---
__global__ void split_xgw(const float4* __restrict__ x, uint2* __restrict__ x16,
                          uint2* __restrict__ gx,
                          const float4* __restrict__ w, uint2* __restrict__ gw)
{
    if (blockIdx.x == 0 && threadIdx.x < E_EXP) g_count[threadIdx.x] = 0;
    if (blockIdx.x < 512) {
        const int n4 = T_TOK * DM / 4;
        int stride = 512 * blockDim.x;
        for (int i = blockIdx.x * blockDim.x + threadIdx.x; i < n4; i += stride) {
            float4 v = __ldg(&x[i]);
            __half hx = __float2half_rn(v.x), hy = __float2half_rn(v.y);
            __half hz = __float2half_rn(v.z), hw = __float2half_rn(v.w);
            uint2 h, l;
            h.x = packh(__half2float(hx), __half2float(hy));
            h.y = packh(__half2float(hz), __half2float(hw));
            l.x = packh(v.x - __half2float(hx), v.y - __half2float(hy));
            l.y = packh(v.z - __half2float(hz), v.w - __half2float(hw));
            x16[i] = h;
            int t  = i >> 7;
            int c4 = i & 127;
            uint2* row = gx + (size_t)t * 384;
            row[c4]       = h;
            row[c4 + 128] = h;
            row[c4 + 256] = l;
        }
    } else {
        const int n4 = DM * H_GATE / 4;
        int stride = 512 * blockDim.x;
        for (int i = (blockIdx.x - 512) * blockDim.x + threadIdx.x; i < n4; i += stride) {
            float4 v = __ldg(&w[i]);
            __half hx = __float2half_rn(v.x), hy = __float2half_rn(v.y);
            __half hz = __float2half_rn(v.z), hw = __float2half_rn(v.w);
            uint2 h, l;
            h.x = packh(__half2float(hx), __half2float(hy));
            h.y = packh(__half2float(hz), __half2float(hw));
            l.x = packh(v.x - __half2float(hx), v.y - __half2float(hy));
            l.y = packh(v.z - __half2float(hz), v.w - __half2float(hw));
            int row = i >> 8;
            int c4  = i & 255;
            gw[(size_t)row * 256 + c4]          = h;
            gw[(size_t)(row + 512) * 256 + c4]  = l;
            gw[(size_t)(row + 1024) * 256 + c4] = h;
        }
    }
}

// ---------------- block table build (single block, 64 threads) ---------------
__global__ void build_btab()
{
    __shared__ int off[E_EXP];
    const int e = threadIdx.x;
    int nb = (g_count[e] + 127) >> 7;
    off[e] = nb;
    __syncthreads();
    if (e == 0) {
        int s = 0;
        for (int i = 0; i < E_EXP; i++) { int t = off[i]; off[i] = s; s += t; }
        g_nblk = s;
    }
    __syncthreads();
    int o = off[e];
    for (int b = 0; b < nb; b++) g_btab[o + b] = make_int2(e, b * 128);
}

// ---------------- all-fp16 grouped GEMM: cp.async + ldmatrix + HMMA ----------
// C[out(r), n] = [w(r)] * ( act( sum_k A[in(r),k]*B[e][k,n] + bias[e][n] ) )
// btab != null: compacted grid, (e, m0) from table. SCALE: scale rows by topkw.
template<typename OT, int ACT, int SCALE>
__global__ __launch_bounds__(256, 2)
void mma_gemm16(const __half* __restrict__ A, int lda, int K,
                const __half* __restrict__ Bbase, size_t strideB, int N,
                const float* __restrict__ biasBase, int strideBias,
                OT* __restrict__ C, int ldc,
                const int* __restrict__ rowlist, const int* __restrict__ outlist,
                const int* __restrict__ cnts, int Mfixed,
                const int2* __restrict__ btab)
{
    int e, m0;
    if (btab) {
        if ((int)blockIdx.x >= g_nblk) return;
        int2 be = btab[blockIdx.x];
        e = be.x; m0 = be.y;
    } else {
        e = blockIdx.z; m0 = blockIdx.x * 128;
    }
    const int M = cnts ? cnts[e] : Mfixed;
    if (m0 >= M) return;
    const int n0 = blockIdx.y * 128;

    extern __shared__ char sm[];
    const uint32_t smBytes = smem_u32(sm);

    const int tid  = threadIdx.x;
    const int wid  = tid >> 5;
    const int lane = tid & 31;
    const int wy   = wid & 3;
    const int wx   = wid >> 2;
    const int g    = lane >> 2;
    const int tig  = lane & 3;

    const int* rl = rowlist ? rowlist + e * T_TOK : nullptr;
    const int* ol = outlist ? outlist + e * T_TOK : nullptr;

    const __half* aSrc[4]; int aSz[4];
    uint32_t aOff0, bOff0;
    const __half* bSrc0;
    {
        int ar = tid >> 3, s = tid & 7;
        aOff0 = (uint32_t)(ar * 128 + 16 * (s ^ (ar & 7)));
        #pragma unroll
        for (int j = 0; j < 4; j++) {
            int gm = m0 + ar + j * 32;
            if (gm < M) { aSrc[j] = A + (size_t)(rl ? rl[gm] : gm) * lda + s * 8; aSz[j] = 16; }
            else        { aSrc[j] = A;                                            aSz[j] = 0;  }
        }
        int bk = tid >> 4, s2 = tid & 15;
        bOff0 = 16384u + (uint32_t)(bk * 256 + 16 * (s2 ^ (bk & 7)));
        bSrc0 = Bbase + (size_t)e * strideB + (size_t)bk * N + n0 + s2 * 8;
    }

    const int NC = K / 64;
    const size_t bStep = (size_t)64 * N;

    #define ISSUE(cc) do { \
        uint32_t st = smBytes + (uint32_t)((cc) % 3) * 32768u; \
        _Pragma("unroll") \
        for (int j = 0; j < 4; j++) \
            cp16(st + aOff0 + (uint32_t)j * 4096u, aSrc[j] + (size_t)(cc) * 64, aSz[j]); \
        _Pragma("unroll") \
        for (int j = 0; j < 4; j++) \
            cp16(st + bOff0 + (uint32_t)j * 4096u, bSrc0 + (size_t)j * 16 * N + (size_t)(cc) * bStep, 16); \
        cp_commit(); \
    } while (0)

    ISSUE(0);
    if (NC > 1) ISSUE(1);

    float acc[2][8][4];
    #pragma unroll
    for (int fm = 0; fm < 2; fm++)
        #pragma unroll
        for (int fn = 0; fn < 8; fn++)
            #pragma unroll
            for (int q = 0; q < 4; q++) acc[fm][fn][q] = 0.f;

    const int mlane = wy * 32 + (lane & 15);
    const int aksel = (lane >> 4) & 1;
    const int bklan = lane & 15;
    const int bnsel = ((lane >> 4) & 1) * 8;

    for (int c = 0; c < NC; c++) {
        if (c + 1 < NC) asm volatile("cp.async.wait_group 1;" ::: "memory");
        else            asm volatile("cp.async.wait_group 0;" ::: "memory");
        __syncthreads();

        if (c + 2 < NC) ISSUE(c + 2);

        const uint32_t stA = smBytes + (uint32_t)(c % 3) * 32768u;
        const uint32_t stB = stA + 16384u;

        #pragma unroll
        for (int ks = 0; ks < 4; ks++) {
            const int aseg = ks * 2 + aksel;
            uint32_t a0[4], a1[4];
            {
                int m = mlane;
                ldsm4(a0, stA + m * 128 + 16 * (aseg ^ (m & 7)));
                m = mlane + 16;
                ldsm4(a1, stA + m * 128 + 16 * (aseg ^ (m & 7)));
            }
            const int kk = ks * 16 + bklan;
            const uint32_t brow = stB + kk * 256;
            const int ksw = kk & 7;
            #pragma unroll
            for (int nb = 0; nb < 4; nb++) {
                int nseg = (wx * 64 + nb * 16 + bnsel) >> 3;
                uint32_t bb[4];
                ldsm4t(bb, brow + 16 * (nseg ^ ksw));
                mma_f16(acc[0][2 * nb],     a0, bb[0], bb[1]);
                mma_f16(acc[1][2 * nb],     a1, bb[0], bb[1]);
                mma_f16(acc[0][2 * nb + 1], a0, bb[2], bb[3]);
                mma_f16(acc[1][2 * nb + 1], a1, bb[2], bb[3]);
            }
        }
    }
    #undef ISSUE

    // ---- epilogue -----------------------------------------------------------
    const float* bias = biasBase ? biasBase + (size_t)e * strideBias + n0 : nullptr;
    #pragma unroll
    for (int fm = 0; fm < 2; fm++) {
        int r0 = m0 + wy * 32 + fm * 16 + g;
        #pragma unroll
        for (int half = 0; half < 2; half++) {
            int row = r0 + half * 8;
            if (row >= M) continue;
            int orow = ol ? ol[row] : row;
            float wgt = 1.f;
            if (SCALE) wgt = g_topkw[orow];
            OT* cp = C + (size_t)orow * ldc + n0;
            #pragma unroll
            for (int fn = 0; fn < 8; fn++) {
                int col = wx * 64 + fn * 8 + 2 * tig;
                float v0 = acc[fm][fn][half * 2 + 0] + (bias ? bias[col]     : 0.f);
                float v1 = acc[fm][fn][half * 2 + 1] + (bias ? bias[col + 1] : 0.f);
                if (ACT == 1) { v0 = fmaxf(v0, 0.f); v1 = fmaxf(v1, 0.f); }
                if (ACT == 2) {
                    v0 = 0.5f * v0 * (1.f + erff(v0 * 0.70710678118654752f));
                    v1 = 0.5f * v1 * (1.f + erff(v1 * 0.70710678118654752f));
                }
                if (SCALE) { v0 *= wgt; v1 *= wgt; }
                if (sizeof(OT) == 4) {
                    *(float2*)((float*)cp + col) = make_float2(v0, v1);
                } else {
                    *(uint32_t*)((__half*)cp + col) = packh(v0, v1);
                }
            }
        }
    }
}

// ---------------- gating: warp-per-token logits + softmax + top-8 ------------
__global__ __launch_bounds__(256)
void gate_route_kernel(const float* __restrict__ h,
                       const float* __restrict__ w2,
                       const float* __restrict__ b2)
{
    __shared__ float hs[8][H_GATE];
    const int warp = threadIdx.x >> 5;
    const int lane = threadIdx.x & 31;
    const int t0 = blockIdx.x * 8;

    for (int i = threadIdx.x; i < 8 * H_GATE; i += 256)
        hs[i >> 10][i & (H_GATE - 1)] = h[(size_t)(t0 + (i >> 10)) * H_GATE + (i & (H_GATE - 1))];
    __syncthreads();

    const int t = t0 + warp;
    float a0 = b2[lane], a1 = b2[lane + 32];
    const float* hrow = hs[warp];
    #pragma unroll 4
    for (int kk = 0; kk < H_GATE; kk++) {
        float hv = hrow[kk];
        a0 = fmaf(hv, __ldg(&w2[kk * E_EXP + lane]),      a0);
        a1 = fmaf(hv, __ldg(&w2[kk * E_EXP + lane + 32]), a1);
    }

    float mx = fmaxf(a0, a1);
    #pragma unroll
    for (int s = 16; s; s >>= 1) mx = fmaxf(mx, __shfl_xor_sync(~0u, mx, s));
    float p0 = expf(a0 - mx), p1 = expf(a1 - mx);
    float sum = p0 + p1;
    #pragma unroll
    for (int s = 16; s; s >>= 1) sum += __shfl_xor_sync(~0u, sum, s);
    p0 /= sum; p1 /= sum;
    g_probs[t * E_EXP + lane]      = p0;
    g_probs[t * E_EXP + lane + 32] = p1;

    float v0 = p0, v1 = p1;
    float selw[TOPK]; int seli[TOPK];
    #pragma unroll
    for (int k = 0; k < TOPK; k++) {
        float v; int idx;
        if (v0 >= v1) { v = v0; idx = lane; } else { v = v1; idx = lane + 32; }
        #pragma unroll
        for (int s = 16; s; s >>= 1) {
            float ov = __shfl_xor_sync(~0u, v, s);
            int   oi = __shfl_xor_sync(~0u, idx, s);
            if (ov > v || (ov == v && oi < idx)) { v = ov; idx = oi; }
        }
        selw[k] = v; seli[k] = idx;
        if (idx == lane) v0 = -1.f;
        else if (idx == lane + 32) v1 = -1.f;
    }

    if (lane == 0) {
        float s8 = 0.f;
        #pragma unroll
        for (int k = 0; k < TOPK; k++) s8 += selw[k];
        float inv = 1.f / s8;
        #pragma unroll
        for (int k = 0; k < TOPK; k++) {
            int ee = seli[k];
            g_topkw[t * TOPK + k] = selw[k] * inv;
            int pos = atomicAdd(&g_count[ee], 1);
            g_list_t[ee * T_TOK + pos] = t;
            g_list_p[ee * T_TOK + pos] = t * TOPK + k;
        }
    }
}

// ---------------- load-balance loss (coalesced two-phase) --------------------
__global__ void usage_part()
{
    __shared__ float red[4][E_EXP];
    const int b   = blockIdx.x;
    const int e   = threadIdx.x & 63;
    const int sub = threadIdx.x >> 6;
    float s = 0.f;
    #pragma unroll
    for (int i = 0; i < 16; i++) {
        int t = b * 64 + i * 4 + sub;
        s += g_probs[t * E_EXP + e];
    }
    red[sub][e] = s; __syncthreads();
    if (sub == 0)
        g_part[b][e] = red[0][e] + red[1][e] + red[2][e] + red[3][e];
}
__global__ void lb_final(float* __restrict__ out, int out_size)
{
    __shared__ float red[E_EXP];
    const int e = threadIdx.x;
    float s = 0.f;
    #pragma unroll
    for (int b = 0; b < UPART; b++) s += g_part[b][e];
    float u = s / (float)T_TOK - 1.f / (float)E_EXP;
    red[e] = u * u; __syncthreads();
    for (int st = 32; st > 0; st >>= 1) { if (e < st) red[e] += red[e + st]; __syncthreads(); }
    if (e == 0 && out_size > T_TOK * DM)
        out[T_TOK * DM] = 0.01f * red[0] / (float)E_EXP;
}

// ---------------- combine: plain 8-row sum (rows pre-scaled in GEMM2) --------
__global__ __launch_bounds__(128)
void combine_kernel(float* __restrict__ out)
{
    const int t = blockIdx.x;
    const int d4 = threadIdx.x;
    const float4* yb = (const float4*)g_ybuf;
    float4 a = make_float4(0.f, 0.f, 0.f, 0.f);
    #pragma unroll
    for (int k = 0; k < TOPK; k++) {
        float4 y = yb[(size_t)(t * TOPK + k) * (DM / 4) + d4];
        a.x += y.x; a.y += y.y; a.z += y.z; a.w += y.w;
    }
    ((float4*)out)[(size_t)t * (DM / 4) + d4] = a;
}

// ---------------- launch ------------------------------------------------------
extern "C" void kernel_launch(void* const* d_in, const int* in_sizes, int n_in,
                              void* d_out, int out_size)
{
    const float* x   = (const float*)d_in[0];
    const float* gw1 = (const float*)d_in[1];
    const float* gb1 = (const float*)d_in[2];
    const float* gw2 = (const float*)d_in[3];
    const float* gb2 = (const float*)d_in[4];
    const float* ew1 = (const float*)d_in[5];
    const float* eb1 = (const float*)d_in[6];
    const float* ew2 = (const float*)d_in[7];
    const float* eb2 = (const float*)d_in[8];
    float* out = (float*)d_out;

    float *ph, *pybuf;
    __half *phid, *px16, *pgx, *pgw, *pw1h, *pw2h;
    int *pcnt, *plt, *plp;
    int2* pbtab;
    cudaGetSymbolAddress((void**)&ph,    g_h);
    cudaGetSymbolAddress((void**)&phid,  g_hidden16);
    cudaGetSymbolAddress((void**)&px16,  g_x16);
    cudaGetSymbolAddress((void**)&pgx,   g_gx);
    cudaGetSymbolAddress((void**)&pgw,   g_gw);
    cudaGetSymbolAddress((void**)&pw1h,  g_w1h);
    cudaGetSymbolAddress((void**)&pw2h,  g_w2h);
    cudaGetSymbolAddress((void**)&pybuf, g_ybuf);
    cudaGetSymbolAddress((void**)&pcnt,  g_count);
    cudaGetSymbolAddress((void**)&plt,   g_list_t);
    cudaGetSymbolAddress((void**)&plp,   g_list_p);
    cudaGetSymbolAddress((void**)&pbtab, g_btab);

    const int SMEM_DYN = 3 * 32768;   // 96 KB
    cudaFuncSetAttribute((const void*)mma_gemm16<float, 1, 0>,
                         cudaFuncAttributeMaxDynamicSharedMemorySize, SMEM_DYN);
    cudaFuncSetAttribute((const void*)mma_gemm16<__half, 2, 0>,
                         cudaFuncAttributeMaxDynamicSharedMemorySize, SMEM_DYN);
    cudaFuncSetAttribute((const void*)mma_gemm16<float, 0, 1>,
                         cudaFuncAttributeMaxDynamicSharedMemorySize, SMEM_DYN);

    // fused weight conversion (w1 + w2 in one saturating launch)
    {
        int n8w = (E_EXP * DM * H_EXP) / 8;
        cvt16_w<<<8192, 256>>>((const float4*)ew1, (uint4*)pw1h,
                               (const float4*)ew2, (uint4*)pw2h, n8w);
    }

    // fused splits (x -> x16/gx, gw1 -> gw; also zeroes counts)
    split_xgw<<<1024, 256>>>((const float4*)x, (uint2*)px16, (uint2*)pgx,
                             (const float4*)gw1, (uint2*)pgw);

    // gate layer 1, single error-compensated GEMM (K=1536, fp32-class)
    mma_gemm16<float, 1, 0><<<dim3(T_TOK/128, H_GATE/128, 1), 256, SMEM_DYN>>>(
        pgx, KGATE, KGATE, pgw, 0, H_GATE, gb1, 0,
        ph, H_GATE, nullptr, nullptr, nullptr, T_TOK, nullptr);

    gate_route_kernel<<<T_TOK / 8, 256>>>(ph, gw2, gb2);

    build_btab<<<1, E_EXP>>>();

    usage_part<<<UPART, 256>>>();
    lb_final<<<1, E_EXP>>>(out, out_size);

    // expert GEMM 1 (compacted grid): hidden16 = gelu(x16[list] @ w1h[e] + eb1)
    mma_gemm16<__half, 2, 0><<<dim3(MAXBLK, H_EXP/128, 1), 256, SMEM_DYN>>>(
        px16, DM, DM, pw1h, (size_t)DM * H_EXP, H_EXP, eb1, H_EXP,
        phid, H_EXP, plt, plp, pcnt, 0, pbtab);

    // expert GEMM 2 (compacted, scaled rows): ybuf = topkw * (hidden16 @ w2h + eb2)
    mma_gemm16<float, 0, 1><<<dim3(MAXBLK, DM/128, 1), 256, SMEM_DYN>>>(
        phid, H_EXP, H_EXP, pw2h, (size_t)H_EXP * DM, DM, eb2, DM,
        pybuf, DM, plp, plp, pcnt, 0, pbtab);

    combine_kernel<<<T_TOK, 128>>>(out);
}

// round 15
// speedup vs baseline: 1.9810x; 1.1482x over previous
#include <cuda_runtime.h>
#include <cuda_fp16.h>
#include <math.h>
#include <stdint.h>

#define T_TOK   2048
#define DM      512
#define E_EXP   64
#define TOPK    8
#define H_GATE  1024
#define H_EXP   2048
#define NPAIR   (T_TOK*TOPK)
#define UPART   32
#define KGATE   1536
#define KGATE2  3072      // logits GEMM K: [h_hi | h_hi | h_lo]
#define NL      128       // logits GEMM N (64 experts zero-padded to 128)
#define MAXBLK  192

// ---------------- scratch (device globals) ----------------------------------
static __device__ float  g_h[(size_t)T_TOK * H_GATE];
static __device__ float  g_probs[T_TOK * E_EXP];
static __device__ float  g_topkw[T_TOK * TOPK];
static __device__ float  g_part[UPART][E_EXP];
static __device__ int    g_count[E_EXP];
static __device__ int    g_list_t[E_EXP * T_TOK];
static __device__ int    g_list_p[E_EXP * T_TOK];
static __device__ int2   g_btab[MAXBLK + 1];
static __device__ int    g_nblk;
static __device__ __half g_x16[(size_t)T_TOK * DM];
static __device__ __half g_gx[(size_t)T_TOK * KGATE];
static __device__ __half g_gw[(size_t)KGATE * H_GATE];
static __device__ __half g_gx2[(size_t)T_TOK * KGATE2];      // 12 MiB
static __device__ __half g_gw2c[(size_t)KGATE2 * NL];        // 768 KiB
static __device__ float  g_b2pad[NL];
static __device__ float  g_logits[(size_t)T_TOK * NL];       // 1 MiB
static __device__ __half g_w1h[(size_t)E_EXP * DM * H_EXP];
static __device__ __half g_w2h[(size_t)E_EXP * H_EXP * DM];
static __device__ __half g_hidden16[(size_t)NPAIR * H_EXP];
static __device__ float  g_ybuf[(size_t)NPAIR * DM];

// ---------------- helpers ----------------------------------------------------
__device__ __forceinline__ uint32_t smem_u32(const void* p) {
    uint32_t a;
    asm("{ .reg .u64 t; cvta.to.shared.u64 t, %1; cvt.u32.u64 %0, t; }" : "=r"(a) : "l"(p));
    return a;
}
__device__ __forceinline__ uint32_t packh(float lo, float hi) {
    uint32_t r;
    asm("cvt.rn.f16x2.f32 %0, %1, %2;" : "=r"(r) : "f"(hi), "f"(lo));
    return r;
}
__device__ __forceinline__ void cp16(uint32_t dst, const void* src, int srcsize) {
    asm volatile("cp.async.cg.shared.global [%0], [%1], 16, %2;"
                 :: "r"(dst), "l"(src), "r"(srcsize) : "memory");
}
__device__ __forceinline__ void cp_commit() {
    asm volatile("cp.async.commit_group;" ::: "memory");
}
__device__ __forceinline__ void ldsm4(uint32_t* r, uint32_t addr) {
    asm volatile("ldmatrix.sync.aligned.m8n8.x4.shared.b16 {%0,%1,%2,%3}, [%4];"
                 : "=r"(r[0]), "=r"(r[1]), "=r"(r[2]), "=r"(r[3]) : "r"(addr));
}
__device__ __forceinline__ void ldsm4t(uint32_t* r, uint32_t addr) {
    asm volatile("ldmatrix.sync.aligned.m8n8.x4.trans.shared.b16 {%0,%1,%2,%3}, [%4];"
                 : "=r"(r[0]), "=r"(r[1]), "=r"(r[2]), "=r"(r[3]) : "r"(addr));
}
__device__ __forceinline__ void mma_f16(float* c, const uint32_t* a, uint32_t b0, uint32_t b1) {
    asm volatile(
        "mma.sync.aligned.m16n8k16.row.col.f32.f16.f16.f32 "
        "{%0,%1,%2,%3}, {%4,%5,%6,%7}, {%8,%9}, {%0,%1,%2,%3};"
        : "+f"(c[0]), "+f"(c[1]), "+f"(c[2]), "+f"(c[3])
        : "r"(a[0]), "r"(a[1]), "r"(a[2]), "r"(a[3]), "r"(b0), "r"(b1));
}

// ---------------- fused fp32 -> fp16 bulk convert (w1 then w2) ---------------
__global__ void cvt16_w(const float4* __restrict__ w1, uint4* __restrict__ o1,
                        const float4* __restrict__ w2, uint4* __restrict__ o2,
                        int n8each)
{
    int stride = gridDim.x * blockDim.x;
    int total = 2 * n8each;
    for (int i = blockIdx.x * blockDim.x + threadIdx.x; i < total; i += stride) {
        const float4* in; uint4* out; int j;
        if (i < n8each) { in = w1; out = o1; j = i; }
        else            { in = w2; out = o2; j = i - n8each; }
        float4 v0 = __ldg(&in[2 * j]);
        float4 v1 = __ldg(&in[2 * j + 1]);
        uint4 o;
        o.x = packh(v0.x, v0.y); o.y = packh(v0.z, v0.w);
        o.z = packh(v1.x, v1.y); o.w = packh(v1.z, v1.w);
        out[j] = o;
    }
}

// ---- fused split: [0,512) x, [512,1024) gw1, [1024,1088) gw2+b2pad ---------
__global__ void split_xgw(const float4* __restrict__ x, uint2* __restrict__ x16,
                          uint2* __restrict__ gx,
                          const float4* __restrict__ w, uint2* __restrict__ gw,
                          const float4* __restrict__ w2, uint2* __restrict__ gw2c,
                          const float* __restrict__ b2)
{
    if (blockIdx.x == 0 && threadIdx.x < E_EXP) g_count[threadIdx.x] = 0;
    if (blockIdx.x < 512) {
        const int n4 = T_TOK * DM / 4;
        int stride = 512 * blockDim.x;
        for (int i = blockIdx.x * blockDim.x + threadIdx.x; i < n4; i += stride) {
            float4 v = __ldg(&x[i]);
            __half hx = __float2half_rn(v.x), hy = __float2half_rn(v.y);
            __half hz = __float2half_rn(v.z), hw = __float2half_rn(v.w);
            uint2 h, l;
            h.x = packh(__half2float(hx), __half2float(hy));
            h.y = packh(__half2float(hz), __half2float(hw));
            l.x = packh(v.x - __half2float(hx), v.y - __half2float(hy));
            l.y = packh(v.z - __half2float(hz), v.w - __half2float(hw));
            x16[i] = h;
            int t  = i >> 7;
            int c4 = i & 127;
            uint2* row = gx + (size_t)t * 384;
            row[c4]       = h;
            row[c4 + 128] = h;
            row[c4 + 256] = l;
        }
    } else if (blockIdx.x < 1024) {
        const int n4 = DM * H_GATE / 4;
        int stride = 512 * blockDim.x;
        for (int i = (blockIdx.x - 512) * blockDim.x + threadIdx.x; i < n4; i += stride) {
            float4 v = __ldg(&w[i]);
            __half hx = __float2half_rn(v.x), hy = __float2half_rn(v.y);
            __half hz = __float2half_rn(v.z), hw = __float2half_rn(v.w);
            uint2 h, l;
            h.x = packh(__half2float(hx), __half2float(hy));
            h.y = packh(__half2float(hz), __half2float(hw));
            l.x = packh(v.x - __half2float(hx), v.y - __half2float(hy));
            l.y = packh(v.z - __half2float(hz), v.w - __half2float(hw));
            int row = i >> 8;
            int c4  = i & 255;
            gw[(size_t)row * 256 + c4]          = h;
            gw[(size_t)(row + 512) * 256 + c4]  = l;
            gw[(size_t)(row + 1024) * 256 + c4] = h;
        }
    } else {
        // gw2c: [3072][128] halves = [w2_hi; w2_lo; w2_hi], cols 64-127 zero
        if (blockIdx.x == 1024 && threadIdx.x < NL)
            g_b2pad[threadIdx.x] = (threadIdx.x < E_EXP) ? b2[threadIdx.x / 4 * 4 + (threadIdx.x & 3)] : 0.f;
        int i = (blockIdx.x - 1024) * blockDim.x + threadIdx.x;   // 0..16383
        int k  = i >> 4;          // 0..1023
        int e4 = i & 15;          // 0..15 -> cols e4*4..e4*4+3
        float4 v = __ldg(&w2[i]);
        __half hx = __float2half_rn(v.x), hy = __float2half_rn(v.y);
        __half hz = __float2half_rn(v.z), hw = __float2half_rn(v.w);
        uint2 h, l, z;
        h.x = packh(__half2float(hx), __half2float(hy));
        h.y = packh(__half2float(hz), __half2float(hw));
        l.x = packh(v.x - __half2float(hx), v.y - __half2float(hy));
        l.y = packh(v.z - __half2float(hz), v.w - __half2float(hw));
        z.x = 0u; z.y = 0u;
        gw2c[(size_t)k * 32 + e4]                = h;
        gw2c[(size_t)(k + 1024) * 32 + e4]       = l;
        gw2c[(size_t)(k + 2048) * 32 + e4]       = h;
        gw2c[(size_t)k * 32 + e4 + 16]           = z;
        gw2c[(size_t)(k + 1024) * 32 + e4 + 16]  = z;
        gw2c[(size_t)(k + 2048) * 32 + e4 + 16]  = z;
    }
}

// ---------------- h split: g_h -> [h_hi | h_hi | h_lo] fp16 ------------------
__global__ void split_h(const float4* __restrict__ h, uint2* __restrict__ gx2)
{
    const int n4 = T_TOK * H_GATE / 4;
    int stride = gridDim.x * blockDim.x;
    for (int i = blockIdx.x * blockDim.x + threadIdx.x; i < n4; i += stride) {
        float4 v = __ldg(&h[i]);
        __half hx = __float2half_rn(v.x), hy = __float2half_rn(v.y);
        __half hz = __float2half_rn(v.z), hw = __float2half_rn(v.w);
        uint2 hh, l;
        hh.x = packh(__half2float(hx), __half2float(hy));
        hh.y = packh(__half2float(hz), __half2float(hw));
        l.x = packh(v.x - __half2float(hx), v.y - __half2float(hy));
        l.y = packh(v.z - __half2float(hz), v.w - __half2float(hw));
        int t  = i >> 8;            // 256 uint2 per 1024-col row
        int c4 = i & 255;
        uint2* row = gx2 + (size_t)t * 768;   // 3072 halves = 768 uint2
        row[c4]       = hh;
        row[c4 + 256] = hh;
        row[c4 + 512] = l;
    }
}

// ---------------- block table build ------------------------------------------
__global__ void build_btab()
{
    __shared__ int off[E_EXP];
    const int e = threadIdx.x;
    int nb = (g_count[e] + 127) >> 7;
    off[e] = nb;
    __syncthreads();
    if (e == 0) {
        int s = 0;
        for (int i = 0; i < E_EXP; i++) { int t = off[i]; off[i] = s; s += t; }
        g_nblk = s;
    }
    __syncthreads();
    int o = off[e];
    for (int b = 0; b < nb; b++) g_btab[o + b] = make_int2(e, b * 128);
}

// ---------------- all-fp16 grouped GEMM: cp.async + ldmatrix + HMMA ----------
template<typename OT, int ACT, int SCALE>
__global__ __launch_bounds__(256, 2)
void mma_gemm16(const __half* __restrict__ A, int lda, int K,
                const __half* __restrict__ Bbase, size_t strideB, int N,
                const float* __restrict__ biasBase, int strideBias,
                OT* __restrict__ C, int ldc,
                const int* __restrict__ rowlist, const int* __restrict__ outlist,
                const int* __restrict__ cnts, int Mfixed,
                const int2* __restrict__ btab)
{
    int e, m0;
    if (btab) {
        if ((int)blockIdx.x >= g_nblk) return;
        int2 be = btab[blockIdx.x];
        e = be.x; m0 = be.y;
    } else {
        e = blockIdx.z; m0 = blockIdx.x * 128;
    }
    const int M = cnts ? cnts[e] : Mfixed;
    if (m0 >= M) return;
    const int n0 = blockIdx.y * 128;

    extern __shared__ char sm[];
    const uint32_t smBytes = smem_u32(sm);

    const int tid  = threadIdx.x;
    const int wid  = tid >> 5;
    const int lane = tid & 31;
    const int wy   = wid & 3;
    const int wx   = wid >> 2;
    const int g    = lane >> 2;
    const int tig  = lane & 3;

    const int* rl = rowlist ? rowlist + e * T_TOK : nullptr;
    const int* ol = outlist ? outlist + e * T_TOK : nullptr;

    const __half* aSrc[4]; int aSz[4];
    uint32_t aOff0, bOff0;
    const __half* bSrc0;
    {
        int ar = tid >> 3, s = tid & 7;
        aOff0 = (uint32_t)(ar * 128 + 16 * (s ^ (ar & 7)));
        #pragma unroll
        for (int j = 0; j < 4; j++) {
            int gm = m0 + ar + j * 32;
            if (gm < M) { aSrc[j] = A + (size_t)(rl ? rl[gm] : gm) * lda + s * 8; aSz[j] = 16; }
            else        { aSrc[j] = A;                                            aSz[j] = 0;  }
        }
        int bk = tid >> 4, s2 = tid & 15;
        bOff0 = 16384u + (uint32_t)(bk * 256 + 16 * (s2 ^ (bk & 7)));
        bSrc0 = Bbase + (size_t)e * strideB + (size_t)bk * N + n0 + s2 * 8;
    }

    const int NC = K / 64;
    const size_t bStep = (size_t)64 * N;

    #define ISSUE(cc) do { \
        uint32_t st = smBytes + (uint32_t)((cc) % 3) * 32768u; \
        _Pragma("unroll") \
        for (int j = 0; j < 4; j++) \
            cp16(st + aOff0 + (uint32_t)j * 4096u, aSrc[j] + (size_t)(cc) * 64, aSz[j]); \
        _Pragma("unroll") \
        for (int j = 0; j < 4; j++) \
            cp16(st + bOff0 + (uint32_t)j * 4096u, bSrc0 + (size_t)j * 16 * N + (size_t)(cc) * bStep, 16); \
        cp_commit(); \
    } while (0)

    ISSUE(0);
    if (NC > 1) ISSUE(1);

    float acc[2][8][4];
    #pragma unroll
    for (int fm = 0; fm < 2; fm++)
        #pragma unroll
        for (int fn = 0; fn < 8; fn++)
            #pragma unroll
            for (int q = 0; q < 4; q++) acc[fm][fn][q] = 0.f;

    const int mlane = wy * 32 + (lane & 15);
    const int aksel = (lane >> 4) & 1;
    const int bklan = lane & 15;
    const int bnsel = ((lane >> 4) & 1) * 8;

    for (int c = 0; c < NC; c++) {
        if (c + 1 < NC) asm volatile("cp.async.wait_group 1;" ::: "memory");
        else            asm volatile("cp.async.wait_group 0;" ::: "memory");
        __syncthreads();

        if (c + 2 < NC) ISSUE(c + 2);

        const uint32_t stA = smBytes + (uint32_t)(c % 3) * 32768u;
        const uint32_t stB = stA + 16384u;

        #pragma unroll
        for (int ks = 0; ks < 4; ks++) {
            const int aseg = ks * 2 + aksel;
            uint32_t a0[4], a1[4];
            {
                int m = mlane;
                ldsm4(a0, stA + m * 128 + 16 * (aseg ^ (m & 7)));
                m = mlane + 16;
                ldsm4(a1, stA + m * 128 + 16 * (aseg ^ (m & 7)));
            }
            const int kk = ks * 16 + bklan;
            const uint32_t brow = stB + kk * 256;
            const int ksw = kk & 7;
            #pragma unroll
            for (int nb = 0; nb < 4; nb++) {
                int nseg = (wx * 64 + nb * 16 + bnsel) >> 3;
                uint32_t bb[4];
                ldsm4t(bb, brow + 16 * (nseg ^ ksw));
                mma_f16(acc[0][2 * nb],     a0, bb[0], bb[1]);
                mma_f16(acc[1][2 * nb],     a1, bb[0], bb[1]);
                mma_f16(acc[0][2 * nb + 1], a0, bb[2], bb[3]);
                mma_f16(acc[1][2 * nb + 1], a1, bb[2], bb[3]);
            }
        }
    }
    #undef ISSUE

    // ---- epilogue -----------------------------------------------------------
    const float* bias = biasBase ? biasBase + (size_t)e * strideBias + n0 : nullptr;
    #pragma unroll
    for (int fm = 0; fm < 2; fm++) {
        int r0 = m0 + wy * 32 + fm * 16 + g;
        #pragma unroll
        for (int half = 0; half < 2; half++) {
            int row = r0 + half * 8;
            if (row >= M) continue;
            int orow = ol ? ol[row] : row;
            float wgt = 1.f;
            if (SCALE) wgt = g_topkw[orow];
            OT* cp = C + (size_t)orow * ldc + n0;
            #pragma unroll
            for (int fn = 0; fn < 8; fn++) {
                int col = wx * 64 + fn * 8 + 2 * tig;
                float v0 = acc[fm][fn][half * 2 + 0] + (bias ? bias[col]     : 0.f);
                float v1 = acc[fm][fn][half * 2 + 1] + (bias ? bias[col + 1] : 0.f);
                if (ACT == 1) { v0 = fmaxf(v0, 0.f); v1 = fmaxf(v1, 0.f); }
                if (ACT == 2) {
                    v0 = 0.5f * v0 * (1.f + erff(v0 * 0.70710678118654752f));
                    v1 = 0.5f * v1 * (1.f + erff(v1 * 0.70710678118654752f));
                }
                if (SCALE) { v0 *= wgt; v1 *= wgt; }
                if (sizeof(OT) == 4) {
                    *(float2*)((float*)cp + col) = make_float2(v0, v1);
                } else {
                    *(uint32_t*)((__half*)cp + col) = packh(v0, v1);
                }
            }
        }
    }
}

// ---------------- routing: softmax + top-8 from precomputed logits -----------
__global__ __launch_bounds__(256)
void route_kernel(const float* __restrict__ logits)
{
    const int warp = threadIdx.x >> 5;
    const int lane = threadIdx.x & 31;
    const int t = blockIdx.x * 8 + warp;

    float a0 = logits[(size_t)t * NL + lane];
    float a1 = logits[(size_t)t * NL + lane + 32];

    float mx = fmaxf(a0, a1);
    #pragma unroll
    for (int s = 16; s; s >>= 1) mx = fmaxf(mx, __shfl_xor_sync(~0u, mx, s));
    float p0 = expf(a0 - mx), p1 = expf(a1 - mx);
    float sum = p0 + p1;
    #pragma unroll
    for (int s = 16; s; s >>= 1) sum += __shfl_xor_sync(~0u, sum, s);
    p0 /= sum; p1 /= sum;
    g_probs[t * E_EXP + lane]      = p0;
    g_probs[t * E_EXP + lane + 32] = p1;

    float v0 = p0, v1 = p1;
    float selw[TOPK]; int seli[TOPK];
    #pragma unroll
    for (int k = 0; k < TOPK; k++) {
        float v; int idx;
        if (v0 >= v1) { v = v0; idx = lane; } else { v = v1; idx = lane + 32; }
        #pragma unroll
        for (int s = 16; s; s >>= 1) {
            float ov = __shfl_xor_sync(~0u, v, s);
            int   oi = __shfl_xor_sync(~0u, idx, s);
            if (ov > v || (ov == v && oi < idx)) { v = ov; idx = oi; }
        }
        selw[k] = v; seli[k] = idx;
        if (idx == lane) v0 = -1.f;
        else if (idx == lane + 32) v1 = -1.f;
    }

    if (lane == 0) {
        float s8 = 0.f;
        #pragma unroll
        for (int k = 0; k < TOPK; k++) s8 += selw[k];
        float inv = 1.f / s8;
        #pragma unroll
        for (int k = 0; k < TOPK; k++) {
            int ee = seli[k];
            g_topkw[t * TOPK + k] = selw[k] * inv;
            int pos = atomicAdd(&g_count[ee], 1);
            g_list_t[ee * T_TOK + pos] = t;
            g_list_p[ee * T_TOK + pos] = t * TOPK + k;
        }
    }
}

// ---------------- load-balance loss -------------------------------------------
__global__ void usage_part()
{
    __shared__ float red[4][E_EXP];
    const int b   = blockIdx.x;
    const int e   = threadIdx.x & 63;
    const int sub = threadIdx.x >> 6;
    float s = 0.f;
    #pragma unroll
    for (int i = 0; i < 16; i++) {
        int t = b * 64 + i * 4 + sub;
        s += g_probs[t * E_EXP + e];
    }
    red[sub][e] = s; __syncthreads();
    if (sub == 0)
        g_part[b][e] = red[0][e] + red[1][e] + red[2][e] + red[3][e];
}
__global__ void lb_final(float* __restrict__ out, int out_size)
{
    __shared__ float red[E_EXP];
    const int e = threadIdx.x;
    float s = 0.f;
    #pragma unroll
    for (int b = 0; b < UPART; b++) s += g_part[b][e];
    float u = s / (float)T_TOK - 1.f / (float)E_EXP;
    red[e] = u * u; __syncthreads();
    for (int st = 32; st > 0; st >>= 1) { if (e < st) red[e] += red[e + st]; __syncthreads(); }
    if (e == 0 && out_size > T_TOK * DM)
        out[T_TOK * DM] = 0.01f * red[0] / (float)E_EXP;
}

// ---------------- combine: plain 8-row sum ------------------------------------
__global__ __launch_bounds__(128)
void combine_kernel(float* __restrict__ out)
{
    const int t = blockIdx.x;
    const int d4 = threadIdx.x;
    const float4* yb = (const float4*)g_ybuf;
    float4 a = make_float4(0.f, 0.f, 0.f, 0.f);
    #pragma unroll
    for (int k = 0; k < TOPK; k++) {
        float4 y = yb[(size_t)(t * TOPK + k) * (DM / 4) + d4];
        a.x += y.x; a.y += y.y; a.z += y.z; a.w += y.w;
    }
    ((float4*)out)[(size_t)t * (DM / 4) + d4] = a;
}

// ---------------- launch ------------------------------------------------------
extern "C" void kernel_launch(void* const* d_in, const int* in_sizes, int n_in,
                              void* d_out, int out_size)
{
    const float* x   = (const float*)d_in[0];
    const float* gw1 = (const float*)d_in[1];
    const float* gb1 = (const float*)d_in[2];
    const float* gw2 = (const float*)d_in[3];
    const float* gb2 = (const float*)d_in[4];
    const float* ew1 = (const float*)d_in[5];
    const float* eb1 = (const float*)d_in[6];
    const float* ew2 = (const float*)d_in[7];
    const float* eb2 = (const float*)d_in[8];
    float* out = (float*)d_out;

    float *ph, *pybuf, *pb2pad, *plogits;
    __half *phid, *px16, *pgx, *pgw, *pgx2, *pgw2c, *pw1h, *pw2h;
    int *pcnt, *plt, *plp;
    int2* pbtab;
    cudaGetSymbolAddress((void**)&ph,     g_h);
    cudaGetSymbolAddress((void**)&phid,   g_hidden16);
    cudaGetSymbolAddress((void**)&px16,   g_x16);
    cudaGetSymbolAddress((void**)&pgx,    g_gx);
    cudaGetSymbolAddress((void**)&pgw,    g_gw);
    cudaGetSymbolAddress((void**)&pgx2,   g_gx2);
    cudaGetSymbolAddress((void**)&pgw2c,  g_gw2c);
    cudaGetSymbolAddress((void**)&pb2pad, g_b2pad);
    cudaGetSymbolAddress((void**)&plogits,g_logits);
    cudaGetSymbolAddress((void**)&pw1h,   g_w1h);
    cudaGetSymbolAddress((void**)&pw2h,   g_w2h);
    cudaGetSymbolAddress((void**)&pybuf,  g_ybuf);
    cudaGetSymbolAddress((void**)&pcnt,   g_count);
    cudaGetSymbolAddress((void**)&plt,    g_list_t);
    cudaGetSymbolAddress((void**)&plp,    g_list_p);
    cudaGetSymbolAddress((void**)&pbtab,  g_btab);

    const int SMEM_DYN = 3 * 32768;   // 96 KB
    cudaFuncSetAttribute((const void*)mma_gemm16<float, 1, 0>,
                         cudaFuncAttributeMaxDynamicSharedMemorySize, SMEM_DYN);
    cudaFuncSetAttribute((const void*)mma_gemm16<float, 0, 0>,
                         cudaFuncAttributeMaxDynamicSharedMemorySize, SMEM_DYN);
    cudaFuncSetAttribute((const void*)mma_gemm16<__half, 2, 0>,
                         cudaFuncAttributeMaxDynamicSharedMemorySize, SMEM_DYN);
    cudaFuncSetAttribute((const void*)mma_gemm16<float, 0, 1>,
                         cudaFuncAttributeMaxDynamicSharedMemorySize, SMEM_DYN);

    // fused weight conversion (w1 + w2)
    {
        int n8w = (E_EXP * DM * H_EXP) / 8;
        cvt16_w<<<8192, 256>>>((const float4*)ew1, (uint4*)pw1h,
                               (const float4*)ew2, (uint4*)pw2h, n8w);
    }

    // fused splits (x, gw1, gw2+b2pad; zeroes counts)
    split_xgw<<<1088, 256>>>((const float4*)x, (uint2*)px16, (uint2*)pgx,
                             (const float4*)gw1, (uint2*)pgw,
                             (const float4*)gw2, (uint2*)pgw2c, gb2);

    // gate layer 1: h = relu([x_hi|x_hi|x_lo] @ [w_hi;w_lo;w_hi] + b1)
    mma_gemm16<float, 1, 0><<<dim3(T_TOK/128, H_GATE/128, 1), 256, SMEM_DYN>>>(
        pgx, KGATE, KGATE, pgw, 0, H_GATE, gb1, 0,
        ph, H_GATE, nullptr, nullptr, nullptr, T_TOK, nullptr);

    // logits: split h, then error-compensated GEMM (K=3072, N=128 padded)
    split_h<<<512, 256>>>((const float4*)ph, (uint2*)pgx2);
    mma_gemm16<float, 0, 0><<<dim3(T_TOK/128, NL/128, 1), 256, SMEM_DYN>>>(
        pgx2, KGATE2, KGATE2, pgw2c, 0, NL, pb2pad, 0,
        plogits, NL, nullptr, nullptr, nullptr, T_TOK, nullptr);

    // softmax + top-8 + routing lists
    route_kernel<<<T_TOK / 8, 256>>>(plogits);

    build_btab<<<1, E_EXP>>>();

    usage_part<<<UPART, 256>>>();
    lb_final<<<1, E_EXP>>>(out, out_size);

    // expert GEMM 1 (compacted): hidden16 = gelu(x16[list] @ w1h[e] + eb1)
    mma_gemm16<__half, 2, 0><<<dim3(MAXBLK, H_EXP/128, 1), 256, SMEM_DYN>>>(
        px16, DM, DM, pw1h, (size_t)DM * H_EXP, H_EXP, eb1, H_EXP,
        phid, H_EXP, plt, plp, pcnt, 0, pbtab);

    // expert GEMM 2 (compacted, scaled): ybuf = topkw * (hidden16 @ w2h + eb2)
    mma_gemm16<float, 0, 1><<<dim3(MAXBLK, DM/128, 1), 256, SMEM_DYN>>>(
        phid, H_EXP, H_EXP, pw2h, (size_t)H_EXP * DM, DM, eb2, DM,
        pybuf, DM, plp, plp, pcnt, 0, pbtab);

    combine_kernel<<<T_TOK, 128>>>(out);
}